// round 7
// baseline (speedup 1.0000x reference)
#include <cuda_runtime.h>
#include <cuda_fp16.h>
#include <cstdint>

// DigitCapsules dynamic routing, GB300 sm_103a
// B=256, C=10, I=1152, DI=8, DO=16, 3 routing iterations.
//
// u_hat (fp16, 94.4 MB) is produced once, then routing runs out of SHARED
// MEMORY: a 4-CTA cluster per batch element, each CTA staging its 288-i
// quarter (101 KB padded) into smem and running all 3 iterations on it.
// gmem reads u_hat exactly once. Per-iteration cross-CTA s-reduction via
// float atomicAdd to g_s + threadfence + cluster.sync (co-scheduling makes
// the barrier deadlock-free); every CTA then squashes the full s locally.

#define BSZ   256
#define CCL   10
#define ICAP  1152
#define DOV   16
#define DIV   8
#define QSPL  4                 // CTAs (i-quarters) per cluster
#define ISL   (ICAP / QSPL)     // 288
#define NTILE (ISL / 32)        // 9 tiles of 32 capsules

// Padded smem layout per class: capsule i at byte i*32 + (i>>2)*16
// (16-B hole every 4 capsules -> conflict-free LDS.128 at 32-B lane stride)
#define C_STRIDE  (ISL * 32 + (ISL / 4) * 16)     // 10368 B
#define UH_BYTES  (CCL * C_STRIDE)                // 103680 B
#define ES_FLOATS (2 * CCL * 33)                  // double-buffered exp exchange
#define SMEM_BYTES (UH_BYTES + ES_FLOATS * 4)     // 106320 B

__device__ __align__(256) __half g_uhat[(size_t)BSZ * CCL * ICAP * DOV]; // 94.4 MB
__device__ __align__(256) float g_s[3 * BSZ * CCL * DOV];                // 480 KB

static __device__ __forceinline__ unsigned int pack_h2(float a, float b) {
    __half2 h = __floats2half2_rn(a, b);
    return *reinterpret_cast<unsigned int*>(&h);
}

// ---------------------------------------------------------------------------
__global__ void zero_s_kernel() {
    int t = blockIdx.x * blockDim.x + threadIdx.x;
    if (t < 3 * BSZ * CCL * DOV) g_s[t] = 0.0f;
}

// ---------------------------------------------------------------------------
// K_uhat (R4 version): u_hat[b,c,i,do] = sum_k W[c,i,0,do,k] * x[b,i,k]
// grid = I, 256 threads = b. W rows staged in smem, x row in registers.
// ---------------------------------------------------------------------------
__global__ __launch_bounds__(256) void uhat_kernel(
    const float* __restrict__ x, const float* __restrict__ W)
{
    const int i = blockIdx.x;
    const int b = threadIdx.x;

    __shared__ float4 Ws[CCL * DOV * 2];   // 5120 B

    for (int f = threadIdx.x; f < CCL * DOV * 2; f += 256) {
        int c = f >> 5, rem = f & 31, d = rem >> 1, h = rem & 1;
        Ws[f] = *reinterpret_cast<const float4*>(
            W + ((((size_t)c * ICAP + i) * DOV) + d) * DIV + h * 4);
    }

    const float* xp = x + (size_t)b * (ICAP * DIV) + (size_t)i * DIV;
    const float4 x0 = *reinterpret_cast<const float4*>(xp);
    const float4 x1 = *reinterpret_cast<const float4*>(xp + 4);

    __syncthreads();

    __half* up = g_uhat + (size_t)b * (CCL * ICAP * DOV) + (size_t)i * DOV;

    #pragma unroll
    for (int c = 0; c < CCL; c++) {
        float r[DOV];
        #pragma unroll
        for (int d = 0; d < DOV; d++) {
            float4 w0 = Ws[c * 32 + d * 2];
            float4 w1 = Ws[c * 32 + d * 2 + 1];
            float v = w0.x * x0.x;
            v = fmaf(w0.y, x0.y, v); v = fmaf(w0.z, x0.z, v); v = fmaf(w0.w, x0.w, v);
            v = fmaf(w1.x, x1.x, v); v = fmaf(w1.y, x1.y, v);
            v = fmaf(w1.z, x1.z, v); v = fmaf(w1.w, x1.w, v);
            r[d] = v;
        }
        uint4 q0, q1;
        q0.x = pack_h2(r[0],  r[1]);  q0.y = pack_h2(r[2],  r[3]);
        q0.z = pack_h2(r[4],  r[5]);  q0.w = pack_h2(r[6],  r[7]);
        q1.x = pack_h2(r[8],  r[9]);  q1.y = pack_h2(r[10], r[11]);
        q1.z = pack_h2(r[12], r[13]); q1.w = pack_h2(r[14], r[15]);
        __half* o = up + (size_t)c * (ICAP * DOV);
        *reinterpret_cast<uint4*>(o)     = q0;
        *reinterpret_cast<uint4*>(o + 8) = q1;
    }
}

// unpack one capsule (2x uint4 of half2) into 16 floats
static __device__ __forceinline__ void unpack16(const uint4& a, const uint4& b,
                                                float* __restrict__ u) {
    const __half2* ha = reinterpret_cast<const __half2*>(&a);
    const __half2* hb = reinterpret_cast<const __half2*>(&b);
    #pragma unroll
    for (int q = 0; q < 4; q++) {
        float2 f = __half22float2(ha[q]);
        u[q * 2] = f.x; u[q * 2 + 1] = f.y;
    }
    #pragma unroll
    for (int q = 0; q < 4; q++) {
        float2 f = __half22float2(hb[q]);
        u[8 + q * 2] = f.x; u[8 + q * 2 + 1] = f.y;
    }
}

static __device__ __forceinline__ void cluster_barrier() {
    asm volatile("barrier.cluster.arrive.aligned;" ::: "memory");
    asm volatile("barrier.cluster.wait.aligned;"   ::: "memory");
}

// ---------------------------------------------------------------------------
// route_kernel: cluster of QSPL CTAs per batch element b.
// blockIdx.x = b*QSPL + q. 320 threads: warp = class c, lane = capsule slot.
// Stage u_hat quarter -> smem; 3 iterations on smem; s summed across the
// cluster through g_s atomics + cluster.sync each iteration.
// ---------------------------------------------------------------------------
__global__ void __cluster_dims__(QSPL, 1, 1) __launch_bounds__(320, 2)
route_kernel(float* __restrict__ out)
{
    extern __shared__ unsigned char smem_raw[];
    float* e_s = reinterpret_cast<float*>(smem_raw + UH_BYTES); // [2][CCL][33]

    const int bid = blockIdx.x;
    const int b   = bid >> 2;
    const int q   = bid & (QSPL - 1);
    const int c   = threadIdx.x >> 5;
    const int ii  = threadIdx.x & 31;

    // ---- stage this CTA's u_hat quarter into padded smem
    for (int e = threadIdx.x; e < CCL * ISL * 2; e += 320) {
        const int cc  = e / (ISL * 2);
        const int rem = e - cc * (ISL * 2);
        const int i   = rem >> 1;
        const int h   = rem & 1;
        const uint4 v = *reinterpret_cast<const uint4*>(
            g_uhat + ((size_t)b * CCL + cc) * (size_t)ICAP * DOV
                   + (size_t)(q * ISL + i) * DOV + h * 8);
        *reinterpret_cast<uint4*>(
            smem_raw + cc * C_STRIDE + i * 32 + (i >> 2) * 16 + h * 16) = v;
    }
    __syncthreads();

    const unsigned char* uc = smem_raw + c * C_STRIDE;

    float vr[DOV];
    #pragma unroll
    for (int j = 0; j < DOV; j++) vr[j] = 0.0f;

    #pragma unroll 1
    for (int t = 0; t < 3; t++) {
        float sac[DOV];
        #pragma unroll
        for (int j = 0; j < DOV; j++) sac[j] = 0.0f;

        if (t == 0) {
            // uniform weights 0.1 (softmax of zeros) -- no exchange needed
            for (int ti = 0; ti < NTILE; ti++) {
                const int i = ti * 32 + ii;
                const uint4* p = reinterpret_cast<const uint4*>(
                    uc + i * 32 + (i >> 2) * 16);
                uint4 A = p[0], B = p[1];
                float u[DOV];
                unpack16(A, B, u);
                #pragma unroll
                for (int j = 0; j < DOV; j++) sac[j] = fmaf(0.1f, u[j], sac[j]);
            }
        } else {
            for (int ti = 0; ti < NTILE; ti++) {
                const int i = ti * 32 + ii;
                const uint4* p = reinterpret_cast<const uint4*>(
                    uc + i * 32 + (i >> 2) * 16);
                uint4 A = p[0], B = p[1];
                float u[DOV];
                unpack16(A, B, u);

                float a = u[0] * vr[0];
                #pragma unroll
                for (int j = 1; j < DOV; j++) a = fmaf(u[j], vr[j], a);
                // |logit| bounded (~35): exp safe in fp32 without max-subtract
                const int pb = ti & 1;
                e_s[(pb * CCL + c) * 33 + ii] = __expf(a);
                __syncthreads();

                float Z = e_s[(pb * CCL + 0) * 33 + ii];
                #pragma unroll
                for (int cc = 1; cc < CCL; cc++)
                    Z += e_s[(pb * CCL + cc) * 33 + ii];
                float w = __fdividef(e_s[(pb * CCL + c) * 33 + ii], Z);

                #pragma unroll
                for (int j = 0; j < DOV; j++) sac[j] = fmaf(w, u[j], sac[j]);
            }
        }

        // butterfly reduce over the 32 capsule lanes
        #pragma unroll
        for (int off = 16; off > 0; off >>= 1)
            #pragma unroll
            for (int j = 0; j < DOV; j++)
                sac[j] += __shfl_xor_sync(0xffffffffu, sac[j], off);

        // cluster-wide s-sum through gmem atomics
        float* sp = g_s + (((size_t)t * BSZ + b) * CCL + c) * DOV;
        if (ii == 0) {
            #pragma unroll
            for (int j = 0; j < DOV; j++) atomicAdd(sp + j, sac[j]);
            __threadfence();
        }
        cluster_barrier();   // all 4 quarters' partials are in g_s[t] now

        // every CTA computes the identical squash locally
        float s[DOV];
        #pragma unroll
        for (int j = 0; j < DOV; j++) s[j] = __ldcg(sp + j);
        float sq = 0.0f;
        #pragma unroll
        for (int j = 0; j < DOV; j++) sq = fmaf(s[j], s[j], sq);
        float scale = __fdividef(sqrtf(sq), 1.0f + sq);

        if (t == 2) {
            if (q == 0 && ii == 0) {
                float4* op = reinterpret_cast<float4*>(
                    out + ((size_t)b * CCL + c) * DOV);
                op[0] = make_float4(s[0]*scale,  s[1]*scale,  s[2]*scale,  s[3]*scale);
                op[1] = make_float4(s[4]*scale,  s[5]*scale,  s[6]*scale,  s[7]*scale);
                op[2] = make_float4(s[8]*scale,  s[9]*scale,  s[10]*scale, s[11]*scale);
                op[3] = make_float4(s[12]*scale, s[13]*scale, s[14]*scale, s[15]*scale);
            }
        } else {
            #pragma unroll
            for (int j = 0; j < DOV; j++) vr[j] = fmaf(s[j], scale, vr[j]);
        }
    }
}

// ---------------------------------------------------------------------------
extern "C" void kernel_launch(void* const* d_in, const int* in_sizes, int n_in,
                              void* d_out, int out_size)
{
    const float* x = (const float*)d_in[0];
    const float* W = (const float*)d_in[1];
    if (in_sizes[0] == CCL * ICAP * DOV * DIV) {  // defensively identify by size
        const float* t = x; x = W; W = t;
    }
    float* out = (float*)d_out;

    // allow >48 KB dynamic smem (idempotent; not a stream op, capture-safe)
    cudaFuncSetAttribute(route_kernel,
                         cudaFuncAttributeMaxDynamicSharedMemorySize, SMEM_BYTES);

    zero_s_kernel<<<(3 * BSZ * CCL * DOV + 1023) / 1024, 1024>>>();
    uhat_kernel<<<ICAP, 256>>>(x, W);
    route_kernel<<<BSZ * QSPL, 320, SMEM_BYTES>>>(out);
}

// round 8
// speedup vs baseline: 1.2864x; 1.2864x over previous
#include <cuda_runtime.h>
#include <cuda_fp16.h>
#include <cstdint>

// DigitCapsules dynamic routing, GB300 sm_103a
// B=256, C=10, I=1152, DI=8, DO=16, 3 routing iterations.
//
// R8: R4 skeleton (uhat producer + fused 3-iteration route, block = batch
// element, warp = class). Route slimmed to <=64 regs (packed f32x2 state,
// no explicit prefetch) + __launch_bounds__(320,3) -> 3 CTAs/SM, ~30 warps,
// to cover the per-tile latency chains that pinned route at ~52us.

#define BSZ  256
#define CCL  10
#define ICAP 1152
#define DOV  16
#define DIV  8
#define NT   (ICAP / 32)   // 36 tiles of 32 input capsules

typedef unsigned long long ull;

__device__ __align__(256) __half g_uhat[(size_t)BSZ * CCL * ICAP * DOV]; // 94.4 MB

// ---------------- packed f32x2 helpers (exact fp32 SIMD-2) ------------------
static __device__ __forceinline__ ull pack2(float x, float y) {
    ull r; asm("mov.b64 %0, {%1, %2};" : "=l"(r) : "f"(x), "f"(y)); return r;
}
static __device__ __forceinline__ void unpack2(ull v, float& x, float& y) {
    asm("mov.b64 {%0, %1}, %2;" : "=f"(x), "=f"(y) : "l"(v));
}
static __device__ __forceinline__ ull fma2(ull a, ull b, ull c) {
    ull d; asm("fma.rn.f32x2 %0, %1, %2, %3;" : "=l"(d) : "l"(a), "l"(b), "l"(c));
    return d;
}
static __device__ __forceinline__ ull mul2(ull a, ull b) {
    ull d; asm("mul.rn.f32x2 %0, %1, %2;" : "=l"(d) : "l"(a), "l"(b)); return d;
}
static __device__ __forceinline__ ull add2(ull a, ull b) {
    ull d; asm("add.rn.f32x2 %0, %1, %2;" : "=l"(d) : "l"(a), "l"(b)); return d;
}
static __device__ __forceinline__ ull h2f2(__half2 h) {
    float2 f = __half22float2(h);
    return pack2(f.x, f.y);
}
static __device__ __forceinline__ unsigned int pack_h2(float a, float b) {
    __half2 h = __floats2half2_rn(a, b);
    return *reinterpret_cast<unsigned int*>(&h);
}

// ---------------------------------------------------------------------------
// K_uhat (R4 version, proven): u_hat[b,c,i,do] = sum_k W[c,i,0,do,k]*x[b,i,k]
// grid = I (block per input capsule), 256 threads = b.
// ---------------------------------------------------------------------------
__global__ __launch_bounds__(256) void uhat_kernel(
    const float* __restrict__ x, const float* __restrict__ W)
{
    const int i = blockIdx.x;
    const int b = threadIdx.x;

    __shared__ float4 Ws[CCL * DOV * 2];   // 5120 B

    for (int f = threadIdx.x; f < CCL * DOV * 2; f += 256) {
        int c = f >> 5, rem = f & 31, d = rem >> 1, h = rem & 1;
        Ws[f] = *reinterpret_cast<const float4*>(
            W + ((((size_t)c * ICAP + i) * DOV) + d) * DIV + h * 4);
    }

    const float* xp = x + (size_t)b * (ICAP * DIV) + (size_t)i * DIV;
    const float4 x0 = *reinterpret_cast<const float4*>(xp);
    const float4 x1 = *reinterpret_cast<const float4*>(xp + 4);

    __syncthreads();

    __half* up = g_uhat + (size_t)b * (CCL * ICAP * DOV) + (size_t)i * DOV;

    #pragma unroll
    for (int c = 0; c < CCL; c++) {
        float r[DOV];
        #pragma unroll
        for (int d = 0; d < DOV; d++) {
            float4 w0 = Ws[c * 32 + d * 2];
            float4 w1 = Ws[c * 32 + d * 2 + 1];
            float v = w0.x * x0.x;
            v = fmaf(w0.y, x0.y, v); v = fmaf(w0.z, x0.z, v); v = fmaf(w0.w, x0.w, v);
            v = fmaf(w1.x, x1.x, v); v = fmaf(w1.y, x1.y, v);
            v = fmaf(w1.z, x1.z, v); v = fmaf(w1.w, x1.w, v);
            r[d] = v;
        }
        uint4 q0, q1;
        q0.x = pack_h2(r[0],  r[1]);  q0.y = pack_h2(r[2],  r[3]);
        q0.z = pack_h2(r[4],  r[5]);  q0.w = pack_h2(r[6],  r[7]);
        q1.x = pack_h2(r[8],  r[9]);  q1.y = pack_h2(r[10], r[11]);
        q1.z = pack_h2(r[12], r[13]); q1.w = pack_h2(r[14], r[15]);
        __half* o = up + (size_t)c * (ICAP * DOV);
        *reinterpret_cast<uint4*>(o)     = q0;
        *reinterpret_cast<uint4*>(o + 8) = q1;
    }
}

// ---------------------------------------------------------------------------
// route_kernel: all 3 routing iterations for one batch element.
// grid = B, 320 threads: warp = class c, lane ii = capsule slot.
// 3 CTAs/SM (<=64 regs): packed f32x2 state, no explicit prefetch.
// ---------------------------------------------------------------------------
__global__ __launch_bounds__(320, 3) void route_kernel(float* __restrict__ out)
{
    const int b  = blockIdx.x;
    const int c  = threadIdx.x >> 5;
    const int ii = threadIdx.x & 31;

    __shared__ float e_s[2][CCL][33];   // double-buffered exp exchange

    const __half* ub = g_uhat + ((size_t)b * CCL + c) * (size_t)ICAP * DOV
                              + (size_t)ii * DOV;

    ull vrp[8];    // packed running vacc (dims 2j, 2j+1)
    ull sacp[8];   // packed s accumulators

    // ---------------- iteration 0: uniform weights 0.1, no barriers
    {
        const ull w2 = pack2(0.1f, 0.1f);
        #pragma unroll
        for (int j = 0; j < 8; j++) sacp[j] = pack2(0.0f, 0.0f);

        for (int ti = 0; ti < NT; ti++) {
            const uint4* p = reinterpret_cast<const uint4*>(ub + (size_t)ti * 32 * DOV);
            uint4 A = p[0], B = p[1];
            const __half2* ha = reinterpret_cast<const __half2*>(&A);
            const __half2* hb = reinterpret_cast<const __half2*>(&B);
            #pragma unroll
            for (int q = 0; q < 4; q++) sacp[q]     = fma2(w2, h2f2(ha[q]), sacp[q]);
            #pragma unroll
            for (int q = 0; q < 4; q++) sacp[4 + q] = fma2(w2, h2f2(hb[q]), sacp[4 + q]);
        }
    }
    // reduce + squash -> vrp
    {
        float sac[DOV];
        #pragma unroll
        for (int j = 0; j < 8; j++) unpack2(sacp[j], sac[2 * j], sac[2 * j + 1]);
        #pragma unroll
        for (int off = 16; off > 0; off >>= 1)
            #pragma unroll
            for (int j = 0; j < DOV; j++)
                sac[j] += __shfl_xor_sync(0xffffffffu, sac[j], off);
        float sq = 0.0f;
        #pragma unroll
        for (int j = 0; j < DOV; j++) sq = fmaf(sac[j], sac[j], sq);
        float scale = __fdividef(sqrtf(sq), 1.0f + sq);
        #pragma unroll
        for (int j = 0; j < 8; j++)
            vrp[j] = pack2(sac[2 * j] * scale, sac[2 * j + 1] * scale);
    }

    // ---------------- iterations 1 and 2
    #pragma unroll 1
    for (int t = 1; t < 3; t++) {
        #pragma unroll
        for (int j = 0; j < 8; j++) sacp[j] = pack2(0.0f, 0.0f);

        for (int ti = 0; ti < NT; ti++) {
            const uint4* p = reinterpret_cast<const uint4*>(ub + (size_t)ti * 32 * DOV);
            uint4 A = p[0], B = p[1];
            const __half2* ha = reinterpret_cast<const __half2*>(&A);
            const __half2* hb = reinterpret_cast<const __half2*>(&B);

            // dot <u, vacc> with packed FFMA2 (tree-ish: two chains)
            ull d0 = mul2(h2f2(ha[0]), vrp[0]);
            ull d1 = mul2(h2f2(ha[1]), vrp[1]);
            d0 = fma2(h2f2(ha[2]), vrp[2], d0);
            d1 = fma2(h2f2(ha[3]), vrp[3], d1);
            d0 = fma2(h2f2(hb[0]), vrp[4], d0);
            d1 = fma2(h2f2(hb[1]), vrp[5], d1);
            d0 = fma2(h2f2(hb[2]), vrp[6], d0);
            d1 = fma2(h2f2(hb[3]), vrp[7], d1);
            d0 = add2(d0, d1);
            float lo, hi; unpack2(d0, lo, hi);
            float a = lo + hi;

            // |logit| bounded (~35): exp safe in fp32 without max-subtract
            const int pb = ti & 1;
            e_s[pb][c][ii] = __expf(a);
            __syncthreads();

            float Z = e_s[pb][0][ii];
            #pragma unroll
            for (int cc = 1; cc < CCL; cc++) Z += e_s[pb][cc][ii];
            float w = __fdividef(e_s[pb][c][ii], Z);
            ull w2 = pack2(w, w);

            #pragma unroll
            for (int q = 0; q < 4; q++) sacp[q]     = fma2(w2, h2f2(ha[q]), sacp[q]);
            #pragma unroll
            for (int q = 0; q < 4; q++) sacp[4 + q] = fma2(w2, h2f2(hb[q]), sacp[4 + q]);
        }

        float sac[DOV];
        #pragma unroll
        for (int j = 0; j < 8; j++) unpack2(sacp[j], sac[2 * j], sac[2 * j + 1]);
        #pragma unroll
        for (int off = 16; off > 0; off >>= 1)
            #pragma unroll
            for (int j = 0; j < DOV; j++)
                sac[j] += __shfl_xor_sync(0xffffffffu, sac[j], off);

        float sq = 0.0f;
        #pragma unroll
        for (int j = 0; j < DOV; j++) sq = fmaf(sac[j], sac[j], sq);
        float scale = __fdividef(sqrtf(sq), 1.0f + sq);

        if (t == 2) {
            if (ii == 0) {
                float4* op = reinterpret_cast<float4*>(
                    out + ((size_t)b * CCL + c) * DOV);
                op[0] = make_float4(sac[0]*scale,  sac[1]*scale,  sac[2]*scale,  sac[3]*scale);
                op[1] = make_float4(sac[4]*scale,  sac[5]*scale,  sac[6]*scale,  sac[7]*scale);
                op[2] = make_float4(sac[8]*scale,  sac[9]*scale,  sac[10]*scale, sac[11]*scale);
                op[3] = make_float4(sac[12]*scale, sac[13]*scale, sac[14]*scale, sac[15]*scale);
            }
        } else {
            // vacc += squash(s)
            float v0, v1;
            #pragma unroll
            for (int j = 0; j < 8; j++) {
                unpack2(vrp[j], v0, v1);
                vrp[j] = pack2(fmaf(sac[2 * j], scale, v0),
                               fmaf(sac[2 * j + 1], scale, v1));
            }
        }
    }
}

// ---------------------------------------------------------------------------
extern "C" void kernel_launch(void* const* d_in, const int* in_sizes, int n_in,
                              void* d_out, int out_size)
{
    const float* x = (const float*)d_in[0];
    const float* W = (const float*)d_in[1];
    if (in_sizes[0] == CCL * ICAP * DOV * DIV) {  // defensively identify by size
        const float* t = x; x = W; W = t;
    }
    float* out = (float*)d_out;

    uhat_kernel<<<ICAP, 256>>>(x, W);
    route_kernel<<<BSZ, 320>>>(out);
}